// round 2
// baseline (speedup 1.0000x reference)
#include <cuda_runtime.h>
#include <math.h>

#define Bn   32
#define Sn   64
#define Tn   64
#define EMBn 256
#define HIDn 512
#define VOCn 32000

// ---------------- scratch state (device globals; no allocation) ----------------
__device__ __align__(16) float g_kproj[Bn * Sn * HIDn];        // 4 MB
__device__ __align__(16) float g_h0[2][Bn * HIDn];
__device__ __align__(16) float g_h1[2][Bn * HIDn];
__device__ __align__(16) float g_ctx[2][Bn * HIDn];
__device__ __align__(16) float g_dc[Bn * Tn * 2 * HIDn];       // 8 MB  [b*T+t][dec|ctx]

// ---------------- init ----------------
__global__ void init_state_kernel() {
    int i = blockIdx.x * blockDim.x + threadIdx.x;
    if (i < Bn * HIDn) {
        g_h0[0][i] = 0.f;
        g_h1[0][i] = 0.f;
        g_ctx[0][i] = 0.f;
    }
}

// ---------------- generic fp32 GEMM: C[M,N] = A[M,K] * B[N,K]^T (+bias) ----------------
// BM=64, BN=64, BK=16, 256 threads, 4x4 microtile per thread.
#define GBM 64
#define GBN 64
#define GBK 16
__global__ __launch_bounds__(256) void gemm_abt_kernel(
    const float* __restrict__ A, const float* __restrict__ B,
    const float* __restrict__ bias, float* __restrict__ C,
    int M, int N, int K)
{
    __shared__ __align__(16) float As[GBK][GBM + 4];
    __shared__ __align__(16) float Bs[GBK][GBN + 4];

    const int tid = threadIdx.x;
    const int rowBase = blockIdx.y * GBM;
    const int colBase = blockIdx.x * GBN;
    const int tm = tid >> 4;       // 0..15
    const int tn = tid & 15;       // 0..15

    const int lr  = tid >> 2;          // 0..63 (tile row)
    const int lk4 = (tid & 3) * 4;     // 0,4,8,12 (k offset)

    float acc[4][4];
#pragma unroll
    for (int i = 0; i < 4; i++)
#pragma unroll
        for (int j = 0; j < 4; j++) acc[i][j] = 0.f;

    const float* Aptr = A + (size_t)(rowBase + lr) * K + lk4;
    const float* Bptr = B + (size_t)(colBase + lr) * K + lk4;

    for (int kt = 0; kt < K; kt += GBK) {
        float4 a4 = *(const float4*)(Aptr + kt);
        float4 b4 = *(const float4*)(Bptr + kt);
        As[lk4 + 0][lr] = a4.x; As[lk4 + 1][lr] = a4.y;
        As[lk4 + 2][lr] = a4.z; As[lk4 + 3][lr] = a4.w;
        Bs[lk4 + 0][lr] = b4.x; Bs[lk4 + 1][lr] = b4.y;
        Bs[lk4 + 2][lr] = b4.z; Bs[lk4 + 3][lr] = b4.w;
        __syncthreads();

#pragma unroll
        for (int kk = 0; kk < GBK; kk++) {
            float4 av = *(const float4*)(&As[kk][tm * 4]);
            float4 bv = *(const float4*)(&Bs[kk][tn * 4]);
            float ar[4] = {av.x, av.y, av.z, av.w};
            float br[4] = {bv.x, bv.y, bv.z, bv.w};
#pragma unroll
            for (int i = 0; i < 4; i++)
#pragma unroll
                for (int j = 0; j < 4; j++)
                    acc[i][j] = fmaf(ar[i], br[j], acc[i][j]);
        }
        __syncthreads();
    }

    float bv[4] = {0.f, 0.f, 0.f, 0.f};
    if (bias) {
        float4 b4 = *(const float4*)(bias + colBase + tn * 4);
        bv[0] = b4.x; bv[1] = b4.y; bv[2] = b4.z; bv[3] = b4.w;
    }
#pragma unroll
    for (int i = 0; i < 4; i++) {
        float4 o;
        o.x = acc[i][0] + bv[0];
        o.y = acc[i][1] + bv[1];
        o.z = acc[i][2] + bv[2];
        o.w = acc[i][3] + bv[3];
        *(float4*)(C + (size_t)(rowBase + tm * 4 + i) * N + colBase + tn * 4) = o;
    }
}

// ---------------- fused GRU cell step ----------------
// mode 0: layer 0, x = [emb(tgt[b,t]) (256) | ctx_prev (512)], h = g_h0[p]  -> g_h0[1-p]
// mode 1: layer 1, x = g_h0[1-p] (512),                       h = g_h1[p]  -> g_h1[1-p], dec -> g_dc
// grid: (8 j-tiles of 64, B blocks), 256 threads = 4 k-slices x 64 j
__global__ __launch_bounds__(256) void gru_step_kernel(
    int mode, int t, int p,
    const float* __restrict__ emb_table, const int* __restrict__ tgt,
    const float* __restrict__ W_ih, const float* __restrict__ W_hh,
    const float* __restrict__ b_ih, const float* __restrict__ b_hh)
{
    __shared__ __align__(16) float xs[EMBn + HIDn];   // up to 768
    __shared__ __align__(16) float hs[HIDn];
    __shared__ float red[4][4][64];                   // [val][slice][j_local]

    const int b     = blockIdx.y;
    const int jl    = threadIdx.x & 63;
    const int slice = threadIdx.x >> 6;
    const int j     = blockIdx.x * 64 + jl;
    const int KX    = mode ? HIDn : (EMBn + HIDn);

    if (mode == 0) {
        int tok = tgt[b * Tn + t];
        for (int i = threadIdx.x; i < EMBn; i += 256)
            xs[i] = emb_table[(size_t)tok * EMBn + i];
        const float* cx = g_ctx[p] + b * HIDn;
        for (int i = threadIdx.x; i < HIDn; i += 256)
            xs[EMBn + i] = cx[i];
        const float* h = g_h0[p] + b * HIDn;
        for (int i = threadIdx.x; i < HIDn; i += 256)
            hs[i] = h[i];
    } else {
        const float* x = g_h0[1 - p] + b * HIDn;
        for (int i = threadIdx.x; i < HIDn; i += 256)
            xs[i] = x[i];
        const float* h = g_h1[p] + b * HIDn;
        for (int i = threadIdx.x; i < HIDn; i += 256)
            hs[i] = h[i];
    }
    __syncthreads();

    // input-gate dots over this thread's k slice
    const int kxw = KX / 4;               // 192 or 128
    const int kx0 = slice * kxw;
    const float* wr = W_ih + (size_t)j * KX;
    const float* wz = W_ih + (size_t)(j + HIDn) * KX;
    const float* wn = W_ih + (size_t)(j + 2 * HIDn) * KX;
    float ir = 0.f, iz = 0.f, inn = 0.f;
#pragma unroll 4
    for (int k = kx0; k < kx0 + kxw; k += 4) {
        float4 x4 = *(const float4*)(xs + k);
        float4 r4 = *(const float4*)(wr + k);
        float4 z4 = *(const float4*)(wz + k);
        float4 n4 = *(const float4*)(wn + k);
        ir  = fmaf(x4.x, r4.x, fmaf(x4.y, r4.y, fmaf(x4.z, r4.z, fmaf(x4.w, r4.w, ir))));
        iz  = fmaf(x4.x, z4.x, fmaf(x4.y, z4.y, fmaf(x4.z, z4.z, fmaf(x4.w, z4.w, iz))));
        inn = fmaf(x4.x, n4.x, fmaf(x4.y, n4.y, fmaf(x4.z, n4.z, fmaf(x4.w, n4.w, inn))));
    }

    // hidden-gate dots
    const int kh0 = slice * (HIDn / 4);
    const float* ur = W_hh + (size_t)j * HIDn;
    const float* uz = W_hh + (size_t)(j + HIDn) * HIDn;
    const float* un = W_hh + (size_t)(j + 2 * HIDn) * HIDn;
    float hr = 0.f, hz = 0.f, hn = 0.f;
#pragma unroll 4
    for (int k = kh0; k < kh0 + HIDn / 4; k += 4) {
        float4 h4 = *(const float4*)(hs + k);
        float4 r4 = *(const float4*)(ur + k);
        float4 z4 = *(const float4*)(uz + k);
        float4 n4 = *(const float4*)(un + k);
        hr = fmaf(h4.x, r4.x, fmaf(h4.y, r4.y, fmaf(h4.z, r4.z, fmaf(h4.w, r4.w, hr))));
        hz = fmaf(h4.x, z4.x, fmaf(h4.y, z4.y, fmaf(h4.z, z4.z, fmaf(h4.w, z4.w, hz))));
        hn = fmaf(h4.x, n4.x, fmaf(h4.y, n4.y, fmaf(h4.z, n4.z, fmaf(h4.w, n4.w, hn))));
    }

    red[0][slice][jl] = ir + hr;
    red[1][slice][jl] = iz + hz;
    red[2][slice][jl] = inn;
    red[3][slice][jl] = hn;
    __syncthreads();

    if (slice == 0) {
        float sr  = red[0][0][jl] + red[0][1][jl] + red[0][2][jl] + red[0][3][jl]
                    + b_ih[j] + b_hh[j];
        float sz  = red[1][0][jl] + red[1][1][jl] + red[1][2][jl] + red[1][3][jl]
                    + b_ih[j + HIDn] + b_hh[j + HIDn];
        float xin = red[2][0][jl] + red[2][1][jl] + red[2][2][jl] + red[2][3][jl]
                    + b_ih[j + 2 * HIDn];
        float hnn = red[3][0][jl] + red[3][1][jl] + red[3][2][jl] + red[3][3][jl]
                    + b_hh[j + 2 * HIDn];
        float r = 1.f / (1.f + expf(-sr));
        float z = 1.f / (1.f + expf(-sz));
        float n = tanhf(xin + r * hnn);
        float hnew = (1.f - z) * n + z * hs[j];
        if (mode == 0) {
            g_h0[1 - p][b * HIDn + j] = hnew;
        } else {
            g_h1[1 - p][b * HIDn + j] = hnew;
            g_dc[((size_t)b * Tn + t) * (2 * HIDn) + j] = hnew;   // dec half
        }
    }
}

// ---------------- fused Bahdanau attention step ----------------
// one block per batch b; 256 threads
__global__ __launch_bounds__(256) void attn_step_kernel(
    int t, int p,
    const float* __restrict__ enc, const unsigned char* __restrict__ mask,
    const float* __restrict__ Wq, const float* __restrict__ vvec)
{
    __shared__ __align__(16) float dec[HIDn];
    __shared__ float q[HIDn];
    __shared__ float e[Sn];
    __shared__ float rinv_sh;

    const int b = blockIdx.x;
    const float* h1 = g_h1[1 - p] + b * HIDn;
    for (int i = threadIdx.x; i < HIDn; i += 256) dec[i] = h1[i];
    __syncthreads();

    // q = dec @ Wq^T
    for (int jj = threadIdx.x; jj < HIDn; jj += 256) {
        const float* w = Wq + (size_t)jj * HIDn;
        float s = 0.f;
#pragma unroll 4
        for (int k = 0; k < HIDn; k += 4) {
            float4 w4 = *(const float4*)(w + k);
            s = fmaf(dec[k], w4.x, fmaf(dec[k + 1], w4.y,
                fmaf(dec[k + 2], w4.z, fmaf(dec[k + 3], w4.w, s))));
        }
        q[jj] = s;
    }
    __syncthreads();

    // scores e[s] = v . tanh(q + kproj[b,s,:]), masked
    const int warp = threadIdx.x >> 5, lane = threadIdx.x & 31;
    for (int s0 = warp; s0 < Sn; s0 += 8) {
        const float* kp = g_kproj + ((size_t)b * Sn + s0) * HIDn;
        float acc = 0.f;
        for (int h = lane; h < HIDn; h += 32)
            acc = fmaf(vvec[h], tanhf(q[h] + kp[h]), acc);
#pragma unroll
        for (int o = 16; o; o >>= 1) acc += __shfl_xor_sync(0xFFFFFFFFu, acc, o);
        if (lane == 0) e[s0] = mask[b * Sn + s0] ? -1e9f : acc;
    }
    __syncthreads();

    // softmax over S=64 (serial by thread 0 — tiny)
    if (threadIdx.x == 0) {
        float m = -1e30f;
        for (int s = 0; s < Sn; s++) m = fmaxf(m, e[s]);
        float sum = 0.f;
        for (int s = 0; s < Sn; s++) { float ex = expf(e[s] - m); e[s] = ex; sum += ex; }
        rinv_sh = 1.f / sum;
    }
    __syncthreads();
    const float rinv = rinv_sh;

    // ctx = a @ enc ; store to ctx ping-pong AND to dc buffer (second half)
    for (int h = threadIdx.x; h < HIDn; h += 256) {
        const float* eb = enc + (size_t)b * Sn * HIDn + h;
        float c = 0.f;
#pragma unroll 8
        for (int s = 0; s < Sn; s++) c = fmaf(e[s], eb[(size_t)s * HIDn], c);
        c *= rinv;
        g_ctx[1 - p][b * HIDn + h] = c;
        g_dc[((size_t)b * Tn + t) * (2 * HIDn) + HIDn + h] = c;
    }
}

// ---------------- launch ----------------
extern "C" void kernel_launch(void* const* d_in, const int* in_sizes, int n_in,
                              void* d_out, int out_size)
{
    const float*         enc       = (const float*)d_in[0];
    const unsigned char* src_mask  = (const unsigned char*)d_in[1];
    const int*           tgt_in    = (const int*)d_in[2];
    const float*         emb_table = (const float*)d_in[3];
    const float*         W_ih0     = (const float*)d_in[4];
    const float*         W_hh0     = (const float*)d_in[5];
    const float*         b_ih0     = (const float*)d_in[6];
    const float*         b_hh0     = (const float*)d_in[7];
    const float*         W_ih1     = (const float*)d_in[8];
    const float*         W_hh1     = (const float*)d_in[9];
    const float*         b_ih1     = (const float*)d_in[10];
    const float*         b_hh1     = (const float*)d_in[11];
    const float*         Wq        = (const float*)d_in[12];
    const float*         Wk        = (const float*)d_in[13];
    const float*         vvec      = (const float*)d_in[14];
    const float*         W_out     = (const float*)d_in[15];
    const float*         b_out     = (const float*)d_in[16];
    float*               out       = (float*)d_out;

    float* kproj_ptr = nullptr;
    float* dc_ptr    = nullptr;
    cudaGetSymbolAddress((void**)&kproj_ptr, g_kproj);
    cudaGetSymbolAddress((void**)&dc_ptr, g_dc);

    // zero recurrent state
    init_state_kernel<<<(Bn * HIDn + 255) / 256, 256>>>();

    // k_proj = enc_out @ Wk^T : M=2048, N=512, K=512
    {
        dim3 grid(HIDn / GBN, (Bn * Sn) / GBM);
        gemm_abt_kernel<<<grid, 256>>>(enc, Wk, nullptr, kproj_ptr,
                                       Bn * Sn, HIDn, HIDn);
    }

    // sequential decode
    for (int t = 0; t < Tn; t++) {
        int p = t & 1;
        dim3 ggrid(HIDn / 64, Bn);
        gru_step_kernel<<<ggrid, 256>>>(0, t, p, emb_table, tgt_in,
                                        W_ih0, W_hh0, b_ih0, b_hh0);
        gru_step_kernel<<<ggrid, 256>>>(1, t, p, emb_table, tgt_in,
                                        W_ih1, W_hh1, b_ih1, b_hh1);
        attn_step_kernel<<<Bn, 256>>>(t, p, enc, src_mask, Wq, vvec);
    }

    // logits = dc @ W_out^T + b_out : M=2048, N=32000, K=1024
    {
        dim3 grid(VOCn / GBN, (Bn * Tn) / GBM);
        gemm_abt_kernel<<<grid, 256>>>(dc_ptr, W_out, b_out, out,
                                       Bn * Tn, VOCn, 2 * HIDn);
    }
}

// round 3
// speedup vs baseline: 2.5952x; 2.5952x over previous
#include <cuda_runtime.h>
#include <math.h>

#define Bn   32
#define Sn   64
#define Tn   64
#define EMBn 256
#define HIDn 512
#define VOCn 32000

#define NBLK 128
#define NTHR 256

// ---------------- scratch state (device globals; no allocation) ----------------
__device__ __align__(16) float g_kproj[Bn * Sn * HIDn];        // 4 MB
__device__ __align__(16) float g_h0[2][Bn * HIDn];
__device__ __align__(16) float g_h1[2][Bn * HIDn];
__device__ __align__(16) float g_ctx[2][Bn * HIDn];
__device__ __align__(16) float g_q[Bn * HIDn];
__device__ __align__(16) float g_e[Bn * Sn];
__device__ __align__(16) float g_dc[Bn * Tn * 2 * HIDn];       // 8 MB  [b*T+t][dec|ctx]

__device__ unsigned g_cnt;
__device__ volatile unsigned g_gen;

// ---------------- grid-wide software barrier (all NBLK blocks co-resident) ----
__device__ __forceinline__ void gsync() {
    __syncthreads();
    if (threadIdx.x == 0) {
        unsigned gen0 = g_gen;
        __threadfence();
        unsigned arrived = atomicAdd(&g_cnt, 1u);
        if (arrived == NBLK - 1) {
            atomicExch(&g_cnt, 0u);
            __threadfence();
            g_gen = gen0 + 1u;
        } else {
            while (g_gen == gen0) { __nanosleep(64); }
        }
        __threadfence();
    }
    __syncthreads();
}

// ---------------- dot helpers (per-warp; lane = batch) ----------------
__device__ __forceinline__ void triple16(const float* __restrict__ sx,
    const float* __restrict__ w0, const float* __restrict__ w1,
    const float* __restrict__ w2, float& a0, float& a1, float& a2)
{
#pragma unroll
    for (int i = 0; i < 16; i++) {
        float4 x = *(const float4*)(sx + i * 4);
        float4 u = *(const float4*)(w0 + i * 4);
        float4 v = *(const float4*)(w1 + i * 4);
        float4 s = *(const float4*)(w2 + i * 4);
        a0 = fmaf(x.x, u.x, fmaf(x.y, u.y, fmaf(x.z, u.z, fmaf(x.w, u.w, a0))));
        a1 = fmaf(x.x, v.x, fmaf(x.y, v.y, fmaf(x.z, v.z, fmaf(x.w, v.w, a1))));
        a2 = fmaf(x.x, s.x, fmaf(x.y, s.y, fmaf(x.z, s.z, fmaf(x.w, s.w, a2))));
    }
}

__device__ __forceinline__ void single16(const float* __restrict__ sx,
    const float* __restrict__ w0, float& a0)
{
#pragma unroll
    for (int i = 0; i < 16; i++) {
        float4 x = *(const float4*)(sx + i * 4);
        float4 u = *(const float4*)(w0 + i * 4);
        a0 = fmaf(x.x, u.x, fmaf(x.y, u.y, fmaf(x.z, u.z, fmaf(x.w, u.w, a0))));
    }
}

// ---------------- persistent recurrence kernel ----------------
__global__ __launch_bounds__(NTHR, 1) void decoder_persistent(
    const float* __restrict__ enc, const unsigned char* __restrict__ mask,
    const int* __restrict__ tgt, const float* __restrict__ emb,
    const float* __restrict__ Wih0, const float* __restrict__ Whh0,
    const float* __restrict__ bih0, const float* __restrict__ bhh0,
    const float* __restrict__ Wih1, const float* __restrict__ Whh1,
    const float* __restrict__ bih1, const float* __restrict__ bhh1,
    const float* __restrict__ Wq, const float* __restrict__ vvec)
{
    __shared__ __align__(16) float sX[2][Bn][132];     // padded: bank-conflict-free
    __shared__ float sred[2][4][4][32];                // [khalf][jl][acc][b]
    __shared__ int   sTok[Bn];
    __shared__ float sA[Sn];

    const int tid   = threadIdx.x;
    const int bid   = blockIdx.x;
    const int w     = tid >> 5;
    const int lane  = tid & 31;
    const int jl    = w & 3;
    const int khalf = w >> 2;
    const int j     = bid * 4 + jl;

    // zero initial state (p=0 buffers), 128 floats per block per buffer
    {
        int base = bid * 128;
        if (tid < 128) {
            g_h0[0][base + tid]  = 0.f;
            g_h1[0][base + tid]  = 0.f;
            g_ctx[0][base + tid] = 0.f;
        }
    }
    gsync();

    for (int t = 0; t < Tn; t++) {
        const int p = t & 1;
        const float* h0p  = g_h0[p];     float* h0n  = g_h0[1 - p];
        const float* h1p  = g_h1[p];     float* h1n  = g_h1[1 - p];
        const float* ctxp = g_ctx[p];    float* ctxn = g_ctx[1 - p];

        // ===================== Phase 1: GRU layer 0 =====================
        if (tid < Bn) sTok[tid] = tgt[tid * Tn + t];
        __syncthreads();

        {
            float4 rv[4];
            auto stage = [&](int c) {
#pragma unroll
                for (int r = 0; r < 4; r++) {
                    int idx = r * 256 + tid;
                    int b = idx >> 5, q = idx & 31;
                    const float* src;
                    if (c < 2)      src = emb + (size_t)sTok[b] * EMBn + c * 128;
                    else if (c < 6) src = ctxp + b * HIDn + (c - 2) * 128;
                    else            src = h0p + b * HIDn + (c - 6) * 128;
                    rv[r] = *(const float4*)(src + q * 4);
                }
            };
            auto sts = [&](int buf) {
#pragma unroll
                for (int r = 0; r < 4; r++) {
                    int idx = r * 256 + tid;
                    int b = idx >> 5, q = idx & 31;
                    *(float4*)&sX[buf][b][q * 4] = rv[r];
                }
            };

            float ar = 0.f, az = 0.f, anx = 0.f, anh = 0.f;
            stage(0); sts(0); __syncthreads();
            for (int c = 0; c < 10; c++) {
                if (c < 9) stage(c + 1);
                const float* sx = &sX[c & 1][lane][khalf * 64];
                if (c < 6) {
                    int col = c * 128 + khalf * 64;
                    triple16(sx,
                             Wih0 + (size_t)j * 768 + col,
                             Wih0 + (size_t)(j + 512) * 768 + col,
                             Wih0 + (size_t)(j + 1024) * 768 + col,
                             ar, az, anx);
                } else {
                    int col = (c - 6) * 128 + khalf * 64;
                    triple16(sx,
                             Whh0 + (size_t)j * 512 + col,
                             Whh0 + (size_t)(j + 512) * 512 + col,
                             Whh0 + (size_t)(j + 1024) * 512 + col,
                             ar, az, anh);
                }
                if (c < 9) sts((c + 1) & 1);
                __syncthreads();
            }
            sred[khalf][jl][0][lane] = ar;
            sred[khalf][jl][1][lane] = az;
            sred[khalf][jl][2][lane] = anx;
            sred[khalf][jl][3][lane] = anh;
            __syncthreads();
            if (khalf == 0) {
                ar  += sred[1][jl][0][lane];
                az  += sred[1][jl][1][lane];
                anx += sred[1][jl][2][lane];
                anh += sred[1][jl][3][lane];
                float r = 1.f / (1.f + expf(-(ar + bih0[j] + bhh0[j])));
                float z = 1.f / (1.f + expf(-(az + bih0[j + 512] + bhh0[j + 512])));
                float n = tanhf(anx + bih0[j + 1024] + r * (anh + bhh0[j + 1024]));
                float hp = h0p[lane * HIDn + j];
                h0n[lane * HIDn + j] = (1.f - z) * n + z * hp;
            }
        }
        gsync();

        // ===================== Phase 2: GRU layer 1 =====================
        {
            float4 rv[4];
            auto stage = [&](int c) {
#pragma unroll
                for (int r = 0; r < 4; r++) {
                    int idx = r * 256 + tid;
                    int b = idx >> 5, q = idx & 31;
                    const float* src = (c < 4) ? (h0n + b * HIDn + c * 128)
                                               : (h1p + b * HIDn + (c - 4) * 128);
                    rv[r] = *(const float4*)(src + q * 4);
                }
            };
            auto sts = [&](int buf) {
#pragma unroll
                for (int r = 0; r < 4; r++) {
                    int idx = r * 256 + tid;
                    int b = idx >> 5, q = idx & 31;
                    *(float4*)&sX[buf][b][q * 4] = rv[r];
                }
            };

            float ar = 0.f, az = 0.f, anx = 0.f, anh = 0.f;
            stage(0); sts(0); __syncthreads();
            for (int c = 0; c < 8; c++) {
                if (c < 7) stage(c + 1);
                const float* sx = &sX[c & 1][lane][khalf * 64];
                if (c < 4) {
                    int col = c * 128 + khalf * 64;
                    triple16(sx,
                             Wih1 + (size_t)j * 512 + col,
                             Wih1 + (size_t)(j + 512) * 512 + col,
                             Wih1 + (size_t)(j + 1024) * 512 + col,
                             ar, az, anx);
                } else {
                    int col = (c - 4) * 128 + khalf * 64;
                    triple16(sx,
                             Whh1 + (size_t)j * 512 + col,
                             Whh1 + (size_t)(j + 512) * 512 + col,
                             Whh1 + (size_t)(j + 1024) * 512 + col,
                             ar, az, anh);
                }
                if (c < 7) sts((c + 1) & 1);
                __syncthreads();
            }
            sred[khalf][jl][0][lane] = ar;
            sred[khalf][jl][1][lane] = az;
            sred[khalf][jl][2][lane] = anx;
            sred[khalf][jl][3][lane] = anh;
            __syncthreads();
            if (khalf == 0) {
                ar  += sred[1][jl][0][lane];
                az  += sred[1][jl][1][lane];
                anx += sred[1][jl][2][lane];
                anh += sred[1][jl][3][lane];
                float r = 1.f / (1.f + expf(-(ar + bih1[j] + bhh1[j])));
                float z = 1.f / (1.f + expf(-(az + bih1[j + 512] + bhh1[j + 512])));
                float n = tanhf(anx + bih1[j + 1024] + r * (anh + bhh1[j + 1024]));
                float hp = h1p[lane * HIDn + j];
                float hnew = (1.f - z) * n + z * hp;
                h1n[lane * HIDn + j] = hnew;
                g_dc[((size_t)lane * Tn + t) * (2 * HIDn) + j] = hnew;  // dec half
            }
        }
        gsync();

        // ===================== Phase 3: q = dec @ Wq^T =====================
        {
            float4 rv[4];
            auto stage = [&](int c) {
#pragma unroll
                for (int r = 0; r < 4; r++) {
                    int idx = r * 256 + tid;
                    int b = idx >> 5, q = idx & 31;
                    rv[r] = *(const float4*)(h1n + b * HIDn + c * 128 + q * 4);
                }
            };
            auto sts = [&](int buf) {
#pragma unroll
                for (int r = 0; r < 4; r++) {
                    int idx = r * 256 + tid;
                    int b = idx >> 5, q = idx & 31;
                    *(float4*)&sX[buf][b][q * 4] = rv[r];
                }
            };

            float aq = 0.f;
            stage(0); sts(0); __syncthreads();
            for (int c = 0; c < 4; c++) {
                if (c < 3) stage(c + 1);
                const float* sx = &sX[c & 1][lane][khalf * 64];
                single16(sx, Wq + (size_t)j * 512 + c * 128 + khalf * 64, aq);
                if (c < 3) sts((c + 1) & 1);
                __syncthreads();
            }
            sred[khalf][jl][0][lane] = aq;
            __syncthreads();
            if (khalf == 0) {
                aq += sred[1][jl][0][lane];
                g_q[lane * HIDn + j] = aq;
            }
        }
        gsync();

        // ===================== Phase 4: scores e[b][s] =====================
        {
#pragma unroll
            for (int r = 0; r < 2; r++) {
                int pi = bid * 16 + w * 2 + r;       // 2048 pairs total
                int b = pi >> 6, s = pi & 63;
                const float* qb = g_q + b * HIDn;
                const float* kp = g_kproj + ((size_t)b * Sn + s) * HIDn;
                float acc = 0.f;
#pragma unroll
                for (int i = 0; i < 16; i++) {
                    int h = lane + i * 32;
                    acc = fmaf(vvec[h], tanhf(qb[h] + kp[h]), acc);
                }
#pragma unroll
                for (int o = 16; o; o >>= 1) acc += __shfl_xor_sync(0xFFFFFFFFu, acc, o);
                if (lane == 0) g_e[b * Sn + s] = mask[b * Sn + s] ? -1e9f : acc;
            }
        }
        gsync();

        // ===================== Phase 5: softmax + ctx =====================
        {
            const int b  = bid >> 2;
            const int hs = (bid & 3) * 128;
            if (w == 0) {
                float e0 = g_e[b * Sn + lane];
                float e1 = g_e[b * Sn + 32 + lane];
                float m = fmaxf(e0, e1);
#pragma unroll
                for (int o = 16; o; o >>= 1) m = fmaxf(m, __shfl_xor_sync(0xFFFFFFFFu, m, o));
                float x0 = expf(e0 - m), x1 = expf(e1 - m);
                float ssum = x0 + x1;
#pragma unroll
                for (int o = 16; o; o >>= 1) ssum += __shfl_xor_sync(0xFFFFFFFFu, ssum, o);
                float rinv = 1.f / ssum;
                sA[lane]      = x0 * rinv;
                sA[lane + 32] = x1 * rinv;
            }
            __syncthreads();
            if (tid < 128) {
                int h = hs + tid;
                const float* eb = enc + (size_t)b * Sn * HIDn + h;
                float c = 0.f;
#pragma unroll
                for (int s = 0; s < Sn; s++) c = fmaf(sA[s], eb[(size_t)s * HIDn], c);
                ctxn[b * HIDn + h] = c;
                g_dc[((size_t)b * Tn + t) * (2 * HIDn) + HIDn + h] = c;
            }
        }
        gsync();
    }
}

// ---------------- small fp32 GEMM for kproj: C[M,N] = A[M,K] * B[N,K]^T ------
#define GBM 64
#define GBN 64
#define GBK 16
__global__ __launch_bounds__(256) void gemm_abt_kernel(
    const float* __restrict__ A, const float* __restrict__ B,
    const float* __restrict__ bias, float* __restrict__ C,
    int M, int N, int K)
{
    __shared__ __align__(16) float As[GBK][GBM + 4];
    __shared__ __align__(16) float Bs[GBK][GBN + 4];

    const int tid = threadIdx.x;
    const int rowBase = blockIdx.y * GBM;
    const int colBase = blockIdx.x * GBN;
    const int tm = tid >> 4;
    const int tn = tid & 15;
    const int lr  = tid >> 2;
    const int lk4 = (tid & 3) * 4;

    float acc[4][4];
#pragma unroll
    for (int i = 0; i < 4; i++)
#pragma unroll
        for (int jj = 0; jj < 4; jj++) acc[i][jj] = 0.f;

    const float* Aptr = A + (size_t)(rowBase + lr) * K + lk4;
    const float* Bptr = B + (size_t)(colBase + lr) * K + lk4;

    for (int kt = 0; kt < K; kt += GBK) {
        float4 a4 = *(const float4*)(Aptr + kt);
        float4 b4 = *(const float4*)(Bptr + kt);
        As[lk4 + 0][lr] = a4.x; As[lk4 + 1][lr] = a4.y;
        As[lk4 + 2][lr] = a4.z; As[lk4 + 3][lr] = a4.w;
        Bs[lk4 + 0][lr] = b4.x; Bs[lk4 + 1][lr] = b4.y;
        Bs[lk4 + 2][lr] = b4.z; Bs[lk4 + 3][lr] = b4.w;
        __syncthreads();
#pragma unroll
        for (int kk = 0; kk < GBK; kk++) {
            float4 av = *(const float4*)(&As[kk][tm * 4]);
            float4 bv = *(const float4*)(&Bs[kk][tn * 4]);
            float ar[4] = {av.x, av.y, av.z, av.w};
            float br[4] = {bv.x, bv.y, bv.z, bv.w};
#pragma unroll
            for (int i = 0; i < 4; i++)
#pragma unroll
                for (int jj = 0; jj < 4; jj++)
                    acc[i][jj] = fmaf(ar[i], br[jj], acc[i][jj]);
        }
        __syncthreads();
    }

    float bv[4] = {0.f, 0.f, 0.f, 0.f};
    if (bias) {
        float4 b4 = *(const float4*)(bias + colBase + tn * 4);
        bv[0] = b4.x; bv[1] = b4.y; bv[2] = b4.z; bv[3] = b4.w;
    }
#pragma unroll
    for (int i = 0; i < 4; i++) {
        float4 o;
        o.x = acc[i][0] + bv[0];
        o.y = acc[i][1] + bv[1];
        o.z = acc[i][2] + bv[2];
        o.w = acc[i][3] + bv[3];
        *(float4*)(C + (size_t)(rowBase + tm * 4 + i) * N + colBase + tn * 4) = o;
    }
}

// ---------------- big fp32 vocab GEMM: C[2048,32000] = A[2048,1024]*B^T + bias
#define VBM 128
#define VBN 128
#define VBK 16
#define VK  1024
__global__ __launch_bounds__(256, 2) void gemm_vocab(
    const float* __restrict__ A, const float* __restrict__ B,
    const float* __restrict__ bias, float* __restrict__ C)
{
    __shared__ __align__(16) float As[2][VBK][VBM + 4];
    __shared__ __align__(16) float Bs[2][VBK][VBN + 4];

    const int tid = threadIdx.x;
    const int m0 = blockIdx.x * VBM;
    const int n0 = blockIdx.y * VBN;

    const int lr = tid >> 2;          // 0..63
    const int lk = (tid & 3) * 4;     // 0,4,8,12
    const float* Ap = A + (size_t)(m0 + lr) * VK + lk;
    const float* Bp = B + (size_t)(n0 + lr) * VK + lk;

    const int tm = (tid >> 4) * 4;    // 0..60  (rows tm..tm+3 and tm+64..tm+67)
    const int tn = (tid & 15) * 4;    // 0..60  (cols tn..tn+3 and tn+64..tn+67)

    float acc[8][8];
#pragma unroll
    for (int i = 0; i < 8; i++)
#pragma unroll
        for (int jj = 0; jj < 8; jj++) acc[i][jj] = 0.f;

    float4 a0, a1, b0, b1;
    a0 = *(const float4*)(Ap);
    a1 = *(const float4*)(Ap + 64 * VK);
    b0 = *(const float4*)(Bp);
    b1 = *(const float4*)(Bp + 64 * VK);
    {
        As[0][lk + 0][lr] = a0.x; As[0][lk + 1][lr] = a0.y;
        As[0][lk + 2][lr] = a0.z; As[0][lk + 3][lr] = a0.w;
        As[0][lk + 0][lr + 64] = a1.x; As[0][lk + 1][lr + 64] = a1.y;
        As[0][lk + 2][lr + 64] = a1.z; As[0][lk + 3][lr + 64] = a1.w;
        Bs[0][lk + 0][lr] = b0.x; Bs[0][lk + 1][lr] = b0.y;
        Bs[0][lk + 2][lr] = b0.z; Bs[0][lk + 3][lr] = b0.w;
        Bs[0][lk + 0][lr + 64] = b1.x; Bs[0][lk + 1][lr + 64] = b1.y;
        Bs[0][lk + 2][lr + 64] = b1.z; Bs[0][lk + 3][lr + 64] = b1.w;
    }
    __syncthreads();

    int buf = 0;
    for (int kt = 0; kt < VK; kt += VBK) {
        const bool more = (kt + VBK) < VK;
        if (more) {
            a0 = *(const float4*)(Ap + kt + VBK);
            a1 = *(const float4*)(Ap + kt + VBK + 64 * VK);
            b0 = *(const float4*)(Bp + kt + VBK);
            b1 = *(const float4*)(Bp + kt + VBK + 64 * VK);
        }
#pragma unroll
        for (int kk = 0; kk < VBK; kk++) {
            float4 xa0 = *(const float4*)&As[buf][kk][tm];
            float4 xa1 = *(const float4*)&As[buf][kk][tm + 64];
            float4 xb0 = *(const float4*)&Bs[buf][kk][tn];
            float4 xb1 = *(const float4*)&Bs[buf][kk][tn + 64];
            float av[8] = {xa0.x, xa0.y, xa0.z, xa0.w, xa1.x, xa1.y, xa1.z, xa1.w};
            float bw[8] = {xb0.x, xb0.y, xb0.z, xb0.w, xb1.x, xb1.y, xb1.z, xb1.w};
#pragma unroll
            for (int i = 0; i < 8; i++)
#pragma unroll
                for (int jj = 0; jj < 8; jj++)
                    acc[i][jj] = fmaf(av[i], bw[jj], acc[i][jj]);
        }
        if (more) {
            buf ^= 1;
            As[buf][lk + 0][lr] = a0.x; As[buf][lk + 1][lr] = a0.y;
            As[buf][lk + 2][lr] = a0.z; As[buf][lk + 3][lr] = a0.w;
            As[buf][lk + 0][lr + 64] = a1.x; As[buf][lk + 1][lr + 64] = a1.y;
            As[buf][lk + 2][lr + 64] = a1.z; As[buf][lk + 3][lr + 64] = a1.w;
            Bs[buf][lk + 0][lr] = b0.x; Bs[buf][lk + 1][lr] = b0.y;
            Bs[buf][lk + 2][lr] = b0.z; Bs[buf][lk + 3][lr] = b0.w;
            Bs[buf][lk + 0][lr + 64] = b1.x; Bs[buf][lk + 1][lr + 64] = b1.y;
            Bs[buf][lk + 2][lr + 64] = b1.z; Bs[buf][lk + 3][lr + 64] = b1.w;
            __syncthreads();
        }
    }

    float4 bias0 = *(const float4*)(bias + n0 + tn);
    float4 bias1 = *(const float4*)(bias + n0 + 64 + tn);
    float bv[8] = {bias0.x, bias0.y, bias0.z, bias0.w,
                   bias1.x, bias1.y, bias1.z, bias1.w};
#pragma unroll
    for (int i = 0; i < 8; i++) {
        int row = m0 + ((i < 4) ? (tm + i) : (64 + tm + i - 4));
        float4 o0, o1;
        o0.x = acc[i][0] + bv[0]; o0.y = acc[i][1] + bv[1];
        o0.z = acc[i][2] + bv[2]; o0.w = acc[i][3] + bv[3];
        o1.x = acc[i][4] + bv[4]; o1.y = acc[i][5] + bv[5];
        o1.z = acc[i][6] + bv[6]; o1.w = acc[i][7] + bv[7];
        *(float4*)(C + (size_t)row * VOCn + n0 + tn)      = o0;
        *(float4*)(C + (size_t)row * VOCn + n0 + 64 + tn) = o1;
    }
}

// ---------------- launch ----------------
extern "C" void kernel_launch(void* const* d_in, const int* in_sizes, int n_in,
                              void* d_out, int out_size)
{
    const float*         enc       = (const float*)d_in[0];
    const unsigned char* src_mask  = (const unsigned char*)d_in[1];
    const int*           tgt_in    = (const int*)d_in[2];
    const float*         emb_table = (const float*)d_in[3];
    const float*         W_ih0     = (const float*)d_in[4];
    const float*         W_hh0     = (const float*)d_in[5];
    const float*         b_ih0     = (const float*)d_in[6];
    const float*         b_hh0     = (const float*)d_in[7];
    const float*         W_ih1     = (const float*)d_in[8];
    const float*         W_hh1     = (const float*)d_in[9];
    const float*         b_ih1     = (const float*)d_in[10];
    const float*         b_hh1     = (const float*)d_in[11];
    const float*         Wq        = (const float*)d_in[12];
    const float*         Wk        = (const float*)d_in[13];
    const float*         vvec      = (const float*)d_in[14];
    const float*         W_out     = (const float*)d_in[15];
    const float*         b_out     = (const float*)d_in[16];
    float*               out       = (float*)d_out;

    float* kproj_ptr = nullptr;
    float* dc_ptr    = nullptr;
    cudaGetSymbolAddress((void**)&kproj_ptr, g_kproj);
    cudaGetSymbolAddress((void**)&dc_ptr, g_dc);

    // k_proj = enc_out @ Wk^T : M=2048, N=512, K=512
    {
        dim3 grid(HIDn / GBN, (Bn * Sn) / GBM);
        gemm_abt_kernel<<<grid, 256>>>(enc, Wk, nullptr, kproj_ptr,
                                       Bn * Sn, HIDn, HIDn);
    }

    // full recurrence in one persistent kernel
    decoder_persistent<<<NBLK, NTHR>>>(enc, src_mask, tgt_in, emb_table,
                                       W_ih0, W_hh0, b_ih0, b_hh0,
                                       W_ih1, W_hh1, b_ih1, b_hh1,
                                       Wq, vvec);

    // logits = dc @ W_out^T + b_out : M=2048, N=32000, K=1024
    {
        dim3 grid((Bn * Tn) / VBM, VOCn / VBN);
        gemm_vocab<<<grid, 256>>>(dc_ptr, W_out, b_out, out);
    }
}

// round 5
// speedup vs baseline: 3.3988x; 1.3096x over previous
#include <cuda_runtime.h>
#include <cuda_bf16.h>
#include <math.h>
#include <stdint.h>

#define Bn   32
#define Sn   64
#define Tn   64
#define EMBn 256
#define HIDn 512
#define VOCn 32000
#define KV   1024      // 2*HID

#define NBLK 128
#define NTHR 256

// ---------------- scratch state (device globals; no allocation) ----------------
__device__ __align__(16) float g_kproj[Bn * Sn * HIDn];
__device__ __align__(16) float g_h0[2][Bn * HIDn];
__device__ __align__(16) float g_h1[2][Bn * HIDn];
__device__ __align__(16) float g_ctx[2][Bn * HIDn];
__device__ __align__(16) float g_q[Bn * HIDn];
__device__ __align__(16) float g_e[Bn * Sn];
__device__ __align__(16) float g_dc[Bn * Tn * 2 * HIDn];

__device__ __align__(16) __nv_bfloat16 g_whi[(size_t)VOCn * KV];   // 65.5 MB
__device__ __align__(16) __nv_bfloat16 g_wlo[(size_t)VOCn * KV];   // 65.5 MB
__device__ __align__(16) __nv_bfloat16 g_ahi[Bn * Tn * KV];
__device__ __align__(16) __nv_bfloat16 g_alo[Bn * Tn * KV];

__device__ unsigned g_cnt;
__device__ volatile unsigned g_gen;

// ================= helpers =================
__device__ __forceinline__ uint32_t smem_u32(const void* p) {
    uint32_t a;
    asm("{ .reg .u64 t; cvta.to.shared.u64 t, %1; cvt.u32.u64 %0, t; }" : "=r"(a) : "l"(p));
    return a;
}

__device__ __forceinline__ void cp16(uint32_t dst, const void* src) {
    asm volatile("cp.async.cg.shared.global [%0], [%1], 16;" :: "r"(dst), "l"(src));
}
__device__ __forceinline__ void cp_commit() {
    asm volatile("cp.async.commit_group;" ::: "memory");
}

__device__ __forceinline__ void ldm4(uint32_t& r0, uint32_t& r1, uint32_t& r2,
                                     uint32_t& r3, uint32_t a) {
    asm volatile("ldmatrix.sync.aligned.m8n8.x4.shared.b16 {%0,%1,%2,%3}, [%4];"
                 : "=r"(r0), "=r"(r1), "=r"(r2), "=r"(r3) : "r"(a));
}

__device__ __forceinline__ void mma_bf16(float* c, const uint32_t* a,
                                         uint32_t b0, uint32_t b1) {
    asm volatile(
        "mma.sync.aligned.m16n8k16.row.col.f32.bf16.bf16.f32 "
        "{%0,%1,%2,%3}, {%4,%5,%6,%7}, {%8,%9}, {%0,%1,%2,%3};"
        : "+f"(c[0]), "+f"(c[1]), "+f"(c[2]), "+f"(c[3])
        : "r"(a[0]), "r"(a[1]), "r"(a[2]), "r"(a[3]), "r"(b0), "r"(b1));
}

// ================= split fp32 -> bf16 hi/lo =================
__global__ __launch_bounds__(256) void split_kernel(
    const float* __restrict__ src, __nv_bfloat16* __restrict__ hi,
    __nv_bfloat16* __restrict__ lo, size_t n4)
{
    size_t i = ((size_t)blockIdx.x * 256 + threadIdx.x);
    if (i >= n4) return;
    size_t e = i * 4;
    float4 x = *(const float4*)(src + e);
    __nv_bfloat16 h0 = __float2bfloat16(x.x);
    __nv_bfloat16 h1 = __float2bfloat16(x.y);
    __nv_bfloat16 h2 = __float2bfloat16(x.z);
    __nv_bfloat16 h3 = __float2bfloat16(x.w);
    __nv_bfloat162 hA, hB, lA, lB;
    hA.x = h0; hA.y = h1; hB.x = h2; hB.y = h3;
    lA.x = __float2bfloat16(x.x - __bfloat162float(h0));
    lA.y = __float2bfloat16(x.y - __bfloat162float(h1));
    lB.x = __float2bfloat16(x.z - __bfloat162float(h2));
    lB.y = __float2bfloat16(x.w - __bfloat162float(h3));
    *(__nv_bfloat162*)(hi + e)     = hA;
    *(__nv_bfloat162*)(hi + e + 2) = hB;
    *(__nv_bfloat162*)(lo + e)     = lA;
    *(__nv_bfloat162*)(lo + e + 2) = lB;
}

// ================= HMMA split-bf16 vocab GEMM =================
// C[2048,32000] = (Ahi+Alo) x (Whi+Wlo)^T + bias  via mma.sync bf16 (3 terms)
// CTA tile 128x128, grid (16 m, 250 n). 8 warps = 2(m) x 4(n), warp tile 64x32.
// BK=32, double-buffered cp.async. smem pitch 40 bf16 -> conflict-free ldmatrix.
#define BKv    32
#define PITCH  40
#define ARRE   (128 * PITCH)          // elems per array (5120)
#define STAGEE (4 * ARRE)             // elems per stage (20480)
#define NSTG   (KV / BKv)             // 32

__global__ __launch_bounds__(256, 1) void hmma_gemm_vocab(
    const float* __restrict__ bias, float* __restrict__ C)
{
    extern __shared__ __align__(16) __nv_bfloat16 sm[];
    __shared__ float sBias[128];

    const int tid  = threadIdx.x;
    const int wid  = tid >> 5;
    const int lane = tid & 31;
    const int m0 = blockIdx.x * 128;
    const int n0 = blockIdx.y * 128;

    const int warp_m = wid & 1;        // 0..1
    const int warp_n = wid >> 1;       // 0..3

    if (tid < 128) sBias[tid] = bias[n0 + tid];

    const uint32_t smb = smem_u32(sm);
    const __nv_bfloat16* __restrict__ ahi = g_ahi;
    const __nv_bfloat16* __restrict__ alo = g_alo;
    const __nv_bfloat16* __restrict__ whi = g_whi;
    const __nv_bfloat16* __restrict__ wlo = g_wlo;

    // 2048 16B-chunks per stage, 8 per thread: cidx = i*256+tid
    // arr = cidx>>9, idx = cidx&511, row = idx>>2, c = idx&3
    auto load_stage = [&](int ks, int buf) {
        const int k0 = ks * BKv;
#pragma unroll
        for (int i = 0; i < 8; i++) {
            int cidx = i * 256 + tid;
            int arr  = cidx >> 9;
            int idx  = cidx & 511;
            int row  = idx >> 2;
            int c    = idx & 3;
            const __nv_bfloat16* src;
            if      (arr == 0) src = ahi + (size_t)(m0 + row) * KV + k0 + c * 8;
            else if (arr == 1) src = alo + (size_t)(m0 + row) * KV + k0 + c * 8;
            else if (arr == 2) src = whi + (size_t)(n0 + row) * KV + k0 + c * 8;
            else               src = wlo + (size_t)(n0 + row) * KV + k0 + c * 8;
            uint32_t dst = smb + (uint32_t)(buf * STAGEE + arr * ARRE +
                                            row * PITCH + c * 8) * 2;
            cp16(dst, src);
        }
    };

    float acc[4][4][4];
#pragma unroll
    for (int mt = 0; mt < 4; mt++)
#pragma unroll
        for (int nt = 0; nt < 4; nt++)
#pragma unroll
            for (int r = 0; r < 4; r++) acc[mt][nt][r] = 0.f;

    load_stage(0, 0);
    cp_commit();

    // fragment address components (element offsets within an array)
    const int a_row = warp_m * 64 + (lane & 15);     // + mt*16
    const int a_col = (lane >> 4) * 8;               // + koff
    const int b_row = warp_n * 32 + ((lane >> 4) << 3) + (lane & 7);  // + p*16
    const int b_col = ((lane >> 3) & 1) * 8;         // + koff

    for (int s = 0; s < NSTG; s++) {
        const int buf = s & 1;
        if (s + 1 < NSTG) { load_stage(s + 1, buf ^ 1); cp_commit(); }
        if (s + 1 < NSTG) asm volatile("cp.async.wait_group 1;" ::: "memory");
        else              asm volatile("cp.async.wait_group 0;" ::: "memory");
        __syncthreads();

        const uint32_t sb = smb + (uint32_t)(buf * STAGEE) * 2;
#pragma unroll
        for (int koff = 0; koff < BKv; koff += 16) {
            uint32_t ah[4][4], al[4][4], bh[2][4], bl[2][4];
#pragma unroll
            for (int mt = 0; mt < 4; mt++) {
                uint32_t off = (uint32_t)((a_row + mt * 16) * PITCH + a_col + koff) * 2;
                ldm4(ah[mt][0], ah[mt][1], ah[mt][2], ah[mt][3],
                     sb + 0 * ARRE * 2 + off);
                ldm4(al[mt][0], al[mt][1], al[mt][2], al[mt][3],
                     sb + 1 * ARRE * 2 + off);
            }
#pragma unroll
            for (int p = 0; p < 2; p++) {
                uint32_t off = (uint32_t)((b_row + p * 16) * PITCH + b_col + koff) * 2;
                ldm4(bh[p][0], bh[p][1], bh[p][2], bh[p][3],
                     sb + 2 * ARRE * 2 + off);
                ldm4(bl[p][0], bl[p][1], bl[p][2], bl[p][3],
                     sb + 3 * ARRE * 2 + off);
            }
#pragma unroll
            for (int mt = 0; mt < 4; mt++) {
#pragma unroll
                for (int nt = 0; nt < 4; nt++) {
                    int p = nt >> 1, h = (nt & 1) * 2;
                    mma_bf16(acc[mt][nt], ah[mt], bh[p][h], bh[p][h + 1]);
                    mma_bf16(acc[mt][nt], ah[mt], bl[p][h], bl[p][h + 1]);
                    mma_bf16(acc[mt][nt], al[mt], bh[p][h], bh[p][h + 1]);
                }
            }
        }
        __syncthreads();
    }

    // epilogue: c fragment: (row = lane>>2 [+8], col = (lane&3)*2, pairs)
    const int er = (lane >> 2);
    const int ec = (lane & 3) * 2;
#pragma unroll
    for (int mt = 0; mt < 4; mt++) {
#pragma unroll
        for (int nt = 0; nt < 4; nt++) {
            int row = m0 + warp_m * 64 + mt * 16 + er;
            int colL = warp_n * 32 + nt * 8 + ec;        // 0..127 within tile
            int col = n0 + colL;
            float2 o0, o1;
            o0.x = acc[mt][nt][0] + sBias[colL];
            o0.y = acc[mt][nt][1] + sBias[colL + 1];
            o1.x = acc[mt][nt][2] + sBias[colL];
            o1.y = acc[mt][nt][3] + sBias[colL + 1];
            *(float2*)(C + (size_t)row * VOCn + col)       = o0;
            *(float2*)(C + (size_t)(row + 8) * VOCn + col) = o1;
        }
    }
}

// ---------------- grid-wide software barrier ----------------
__device__ __forceinline__ void gsync() {
    __syncthreads();
    if (threadIdx.x == 0) {
        unsigned gen0 = g_gen;
        __threadfence();
        unsigned arrived = atomicAdd(&g_cnt, 1u);
        if (arrived == NBLK - 1) {
            atomicExch(&g_cnt, 0u);
            __threadfence();
            g_gen = gen0 + 1u;
        } else {
            while (g_gen == gen0) { __nanosleep(64); }
        }
        __threadfence();
    }
    __syncthreads();
}

// ---------------- dot helpers ----------------
__device__ __forceinline__ void triple16(const float* __restrict__ sx,
    const float* __restrict__ w0, const float* __restrict__ w1,
    const float* __restrict__ w2, float& a0, float& a1, float& a2)
{
#pragma unroll
    for (int i = 0; i < 16; i++) {
        float4 x = *(const float4*)(sx + i * 4);
        float4 u = *(const float4*)(w0 + i * 4);
        float4 v = *(const float4*)(w1 + i * 4);
        float4 s = *(const float4*)(w2 + i * 4);
        a0 = fmaf(x.x, u.x, fmaf(x.y, u.y, fmaf(x.z, u.z, fmaf(x.w, u.w, a0))));
        a1 = fmaf(x.x, v.x, fmaf(x.y, v.y, fmaf(x.z, v.z, fmaf(x.w, v.w, a1))));
        a2 = fmaf(x.x, s.x, fmaf(x.y, s.y, fmaf(x.z, s.z, fmaf(x.w, s.w, a2))));
    }
}
__device__ __forceinline__ void single16(const float* __restrict__ sx,
    const float* __restrict__ w0, float& a0)
{
#pragma unroll
    for (int i = 0; i < 16; i++) {
        float4 x = *(const float4*)(sx + i * 4);
        float4 u = *(const float4*)(w0 + i * 4);
        a0 = fmaf(x.x, u.x, fmaf(x.y, u.y, fmaf(x.z, u.z, fmaf(x.w, u.w, a0))));
    }
}

// ---------------- persistent recurrence kernel ----------------
__global__ __launch_bounds__(NTHR, 1) void decoder_persistent(
    const float* __restrict__ enc, const unsigned char* __restrict__ mask,
    const int* __restrict__ tgt, const float* __restrict__ emb,
    const float* __restrict__ Wih0, const float* __restrict__ Whh0,
    const float* __restrict__ bih0, const float* __restrict__ bhh0,
    const float* __restrict__ Wih1, const float* __restrict__ Whh1,
    const float* __restrict__ bih1, const float* __restrict__ bhh1,
    const float* __restrict__ Wq, const float* __restrict__ vvec)
{
    __shared__ __align__(16) float sX[2][Bn][132];
    __shared__ float sred[2][4][4][32];
    __shared__ int   sTok[Bn];
    __shared__ float sA[Sn];

    const int tid   = threadIdx.x;
    const int bid   = blockIdx.x;
    const int w     = tid >> 5;
    const int lane  = tid & 31;
    const int jl    = w & 3;
    const int khalf = w >> 2;
    const int j     = bid * 4 + jl;

    {
        int base = bid * 128;
        if (tid < 128) {
            g_h0[0][base + tid]  = 0.f;
            g_h1[0][base + tid]  = 0.f;
            g_ctx[0][base + tid] = 0.f;
        }
    }
    gsync();

    for (int t = 0; t < Tn; t++) {
        const int p = t & 1;
        const float* h0p  = g_h0[p];     float* h0n  = g_h0[1 - p];
        const float* h1p  = g_h1[p];     float* h1n  = g_h1[1 - p];
        const float* ctxp = g_ctx[p];    float* ctxn = g_ctx[1 - p];

        // Phase 1: GRU0
        if (tid < Bn) sTok[tid] = tgt[tid * Tn + t];
        __syncthreads();
        {
            float4 rv[4];
            auto stage = [&](int c) {
#pragma unroll
                for (int r = 0; r < 4; r++) {
                    int idx = r * 256 + tid;
                    int b = idx >> 5, q = idx & 31;
                    const float* src;
                    if (c < 2)      src = emb + (size_t)sTok[b] * EMBn + c * 128;
                    else if (c < 6) src = ctxp + b * HIDn + (c - 2) * 128;
                    else            src = h0p + b * HIDn + (c - 6) * 128;
                    rv[r] = *(const float4*)(src + q * 4);
                }
            };
            auto sts = [&](int buf) {
#pragma unroll
                for (int r = 0; r < 4; r++) {
                    int idx = r * 256 + tid;
                    int b = idx >> 5, q = idx & 31;
                    *(float4*)&sX[buf][b][q * 4] = rv[r];
                }
            };
            float ar = 0.f, az = 0.f, anx = 0.f, anh = 0.f;
            stage(0); sts(0); __syncthreads();
            for (int c = 0; c < 10; c++) {
                if (c < 9) stage(c + 1);
                const float* sx = &sX[c & 1][lane][khalf * 64];
                if (c < 6) {
                    int col = c * 128 + khalf * 64;
                    triple16(sx, Wih0 + (size_t)j * 768 + col,
                             Wih0 + (size_t)(j + 512) * 768 + col,
                             Wih0 + (size_t)(j + 1024) * 768 + col, ar, az, anx);
                } else {
                    int col = (c - 6) * 128 + khalf * 64;
                    triple16(sx, Whh0 + (size_t)j * 512 + col,
                             Whh0 + (size_t)(j + 512) * 512 + col,
                             Whh0 + (size_t)(j + 1024) * 512 + col, ar, az, anh);
                }
                if (c < 9) sts((c + 1) & 1);
                __syncthreads();
            }
            sred[khalf][jl][0][lane] = ar;
            sred[khalf][jl][1][lane] = az;
            sred[khalf][jl][2][lane] = anx;
            sred[khalf][jl][3][lane] = anh;
            __syncthreads();
            if (khalf == 0) {
                ar  += sred[1][jl][0][lane];
                az  += sred[1][jl][1][lane];
                anx += sred[1][jl][2][lane];
                anh += sred[1][jl][3][lane];
                float r = 1.f / (1.f + expf(-(ar + bih0[j] + bhh0[j])));
                float z = 1.f / (1.f + expf(-(az + bih0[j + 512] + bhh0[j + 512])));
                float n = tanhf(anx + bih0[j + 1024] + r * (anh + bhh0[j + 1024]));
                float hp = h0p[lane * HIDn + j];
                h0n[lane * HIDn + j] = (1.f - z) * n + z * hp;
            }
        }
        gsync();

        // Phase 2: GRU1
        {
            float4 rv[4];
            auto stage = [&](int c) {
#pragma unroll
                for (int r = 0; r < 4; r++) {
                    int idx = r * 256 + tid;
                    int b = idx >> 5, q = idx & 31;
                    const float* src = (c < 4) ? (h0n + b * HIDn + c * 128)
                                               : (h1p + b * HIDn + (c - 4) * 128);
                    rv[r] = *(const float4*)(src + q * 4);
                }
            };
            auto sts = [&](int buf) {
#pragma unroll
                for (int r = 0; r < 4; r++) {
                    int idx = r * 256 + tid;
                    int b = idx >> 5, q = idx & 31;
                    *(float4*)&sX[buf][b][q * 4] = rv[r];
                }
            };
            float ar = 0.f, az = 0.f, anx = 0.f, anh = 0.f;
            stage(0); sts(0); __syncthreads();
            for (int c = 0; c < 8; c++) {
                if (c < 7) stage(c + 1);
                const float* sx = &sX[c & 1][lane][khalf * 64];
                if (c < 4) {
                    int col = c * 128 + khalf * 64;
                    triple16(sx, Wih1 + (size_t)j * 512 + col,
                             Wih1 + (size_t)(j + 512) * 512 + col,
                             Wih1 + (size_t)(j + 1024) * 512 + col, ar, az, anx);
                } else {
                    int col = (c - 4) * 128 + khalf * 64;
                    triple16(sx, Whh1 + (size_t)j * 512 + col,
                             Whh1 + (size_t)(j + 512) * 512 + col,
                             Whh1 + (size_t)(j + 1024) * 512 + col, ar, az, anh);
                }
                if (c < 7) sts((c + 1) & 1);
                __syncthreads();
            }
            sred[khalf][jl][0][lane] = ar;
            sred[khalf][jl][1][lane] = az;
            sred[khalf][jl][2][lane] = anx;
            sred[khalf][jl][3][lane] = anh;
            __syncthreads();
            if (khalf == 0) {
                ar  += sred[1][jl][0][lane];
                az  += sred[1][jl][1][lane];
                anx += sred[1][jl][2][lane];
                anh += sred[1][jl][3][lane];
                float r = 1.f / (1.f + expf(-(ar + bih1[j] + bhh1[j])));
                float z = 1.f / (1.f + expf(-(az + bih1[j + 512] + bhh1[j + 512])));
                float n = tanhf(anx + bih1[j + 1024] + r * (anh + bhh1[j + 1024]));
                float hp = h1p[lane * HIDn + j];
                float hnew = (1.f - z) * n + z * hp;
                h1n[lane * HIDn + j] = hnew;
                g_dc[((size_t)lane * Tn + t) * (2 * HIDn) + j] = hnew;
            }
        }
        gsync();

        // Phase 3: q = dec @ Wq^T
        {
            float4 rv[4];
            auto stage = [&](int c) {
#pragma unroll
                for (int r = 0; r < 4; r++) {
                    int idx = r * 256 + tid;
                    int b = idx >> 5, q = idx & 31;
                    rv[r] = *(const float4*)(h1n + b * HIDn + c * 128 + q * 4);
                }
            };
            auto sts = [&](int buf) {
#pragma unroll
                for (int r = 0; r < 4; r++) {
                    int idx = r * 256 + tid;
                    int b = idx >> 5, q = idx & 31;
                    *(float4*)&sX[buf][b][q * 4] = rv[r];
                }
            };
            float aq = 0.f;
            stage(0); sts(0); __syncthreads();
            for (int c = 0; c < 4; c++) {
                if (c < 3) stage(c + 1);
                const float* sx = &sX[c & 1][lane][khalf * 64];
                single16(sx, Wq + (size_t)j * 512 + c * 128 + khalf * 64, aq);
                if (c < 3) sts((c + 1) & 1);
                __syncthreads();
            }
            sred[khalf][jl][0][lane] = aq;
            __syncthreads();
            if (khalf == 0) {
                aq += sred[1][jl][0][lane];
                g_q[lane * HIDn + j] = aq;
            }
        }
        gsync();

        // Phase 4: scores
        {
#pragma unroll
            for (int r = 0; r < 2; r++) {
                int pi = bid * 16 + w * 2 + r;
                int b = pi >> 6, s = pi & 63;
                const float* qb = g_q + b * HIDn;
                const float* kp = g_kproj + ((size_t)b * Sn + s) * HIDn;
                float acc = 0.f;
#pragma unroll
                for (int i = 0; i < 16; i++) {
                    int h = lane + i * 32;
                    acc = fmaf(vvec[h], tanhf(qb[h] + kp[h]), acc);
                }
#pragma unroll
                for (int o = 16; o; o >>= 1) acc += __shfl_xor_sync(0xFFFFFFFFu, acc, o);
                if (lane == 0) g_e[b * Sn + s] = mask[b * Sn + s] ? -1e9f : acc;
            }
        }
        gsync();

        // Phase 5: softmax + ctx
        {
            const int b  = bid >> 2;
            const int hs = (bid & 3) * 128;
            if (w == 0) {
                float e0 = g_e[b * Sn + lane];
                float e1 = g_e[b * Sn + 32 + lane];
                float m = fmaxf(e0, e1);
#pragma unroll
                for (int o = 16; o; o >>= 1) m = fmaxf(m, __shfl_xor_sync(0xFFFFFFFFu, m, o));
                float x0 = expf(e0 - m), x1 = expf(e1 - m);
                float ssum = x0 + x1;
#pragma unroll
                for (int o = 16; o; o >>= 1) ssum += __shfl_xor_sync(0xFFFFFFFFu, ssum, o);
                float rinv = 1.f / ssum;
                sA[lane]      = x0 * rinv;
                sA[lane + 32] = x1 * rinv;
            }
            __syncthreads();
            if (tid < 128) {
                int h = hs + tid;
                const float* eb = enc + (size_t)b * Sn * HIDn + h;
                float c = 0.f;
#pragma unroll
                for (int s = 0; s < Sn; s++) c = fmaf(sA[s], eb[(size_t)s * HIDn], c);
                ctxn[b * HIDn + h] = c;
                g_dc[((size_t)b * Tn + t) * (2 * HIDn) + HIDn + h] = c;
            }
        }
        gsync();
    }
}

// ---------------- small fp32 GEMM for kproj ----------------
#define GBM 64
#define GBN 64
#define GBK 16
__global__ __launch_bounds__(256) void gemm_abt_kernel(
    const float* __restrict__ A, const float* __restrict__ B,
    float* __restrict__ C, int M, int N, int K)
{
    __shared__ __align__(16) float As[GBK][GBM + 4];
    __shared__ __align__(16) float Bs[GBK][GBN + 4];
    const int tid = threadIdx.x;
    const int rowBase = blockIdx.y * GBM;
    const int colBase = blockIdx.x * GBN;
    const int tm = tid >> 4;
    const int tn = tid & 15;
    const int lr  = tid >> 2;
    const int lk4 = (tid & 3) * 4;

    float acc[4][4];
#pragma unroll
    for (int i = 0; i < 4; i++)
#pragma unroll
        for (int jj = 0; jj < 4; jj++) acc[i][jj] = 0.f;

    const float* Aptr = A + (size_t)(rowBase + lr) * K + lk4;
    const float* Bptr = B + (size_t)(colBase + lr) * K + lk4;
    for (int kt = 0; kt < K; kt += GBK) {
        float4 a4 = *(const float4*)(Aptr + kt);
        float4 b4 = *(const float4*)(Bptr + kt);
        As[lk4 + 0][lr] = a4.x; As[lk4 + 1][lr] = a4.y;
        As[lk4 + 2][lr] = a4.z; As[lk4 + 3][lr] = a4.w;
        Bs[lk4 + 0][lr] = b4.x; Bs[lk4 + 1][lr] = b4.y;
        Bs[lk4 + 2][lr] = b4.z; Bs[lk4 + 3][lr] = b4.w;
        __syncthreads();
#pragma unroll
        for (int kk = 0; kk < GBK; kk++) {
            float4 av = *(const float4*)(&As[kk][tm * 4]);
            float4 bv = *(const float4*)(&Bs[kk][tn * 4]);
            float ar[4] = {av.x, av.y, av.z, av.w};
            float br[4] = {bv.x, bv.y, bv.z, bv.w};
#pragma unroll
            for (int i = 0; i < 4; i++)
#pragma unroll
                for (int jj = 0; jj < 4; jj++)
                    acc[i][jj] = fmaf(ar[i], br[jj], acc[i][jj]);
        }
        __syncthreads();
    }
#pragma unroll
    for (int i = 0; i < 4; i++) {
        float4 o;
        o.x = acc[i][0]; o.y = acc[i][1]; o.z = acc[i][2]; o.w = acc[i][3];
        *(float4*)(C + (size_t)(rowBase + tm * 4 + i) * N + colBase + tn * 4) = o;
    }
}

// ---------------- launch ----------------
extern "C" void kernel_launch(void* const* d_in, const int* in_sizes, int n_in,
                              void* d_out, int out_size)
{
    const float*         enc       = (const float*)d_in[0];
    const unsigned char* src_mask  = (const unsigned char*)d_in[1];
    const int*           tgt_in    = (const int*)d_in[2];
    const float*         emb_table = (const float*)d_in[3];
    const float*         W_ih0     = (const float*)d_in[4];
    const float*         W_hh0     = (const float*)d_in[5];
    const float*         b_ih0     = (const float*)d_in[6];
    const float*         b_hh0     = (const float*)d_in[7];
    const float*         W_ih1     = (const float*)d_in[8];
    const float*         W_hh1     = (const float*)d_in[9];
    const float*         b_ih1     = (const float*)d_in[10];
    const float*         b_hh1     = (const float*)d_in[11];
    const float*         Wq        = (const float*)d_in[12];
    const float*         Wk        = (const float*)d_in[13];
    const float*         vvec      = (const float*)d_in[14];
    const float*         W_out     = (const float*)d_in[15];
    const float*         b_out     = (const float*)d_in[16];
    float*               out       = (float*)d_out;

    float* kproj_ptr = nullptr;
    float* dc_ptr    = nullptr;
    __nv_bfloat16 *whi_p = nullptr, *wlo_p = nullptr, *ahi_p = nullptr, *alo_p = nullptr;
    cudaGetSymbolAddress((void**)&kproj_ptr, g_kproj);
    cudaGetSymbolAddress((void**)&dc_ptr, g_dc);
    cudaGetSymbolAddress((void**)&whi_p, g_whi);
    cudaGetSymbolAddress((void**)&wlo_p, g_wlo);
    cudaGetSymbolAddress((void**)&ahi_p, g_ahi);
    cudaGetSymbolAddress((void**)&alo_p, g_alo);

    const int smem_bytes = 2 * STAGEE * (int)sizeof(__nv_bfloat16);   // 81920
    cudaFuncSetAttribute(hmma_gemm_vocab,
                         cudaFuncAttributeMaxDynamicSharedMemorySize, smem_bytes);

    // split W_out -> bf16 hi/lo
    {
        size_t n4 = (size_t)VOCn * KV / 4;
        split_kernel<<<(unsigned)((n4 + 255) / 256), 256>>>(W_out, whi_p, wlo_p, n4);
    }

    // k_proj = enc_out @ Wk^T
    {
        dim3 grid(HIDn / GBN, (Bn * Sn) / GBM);
        gemm_abt_kernel<<<grid, 256>>>(enc, Wk, kproj_ptr, Bn * Sn, HIDn, HIDn);
    }

    // full recurrence
    decoder_persistent<<<NBLK, NTHR>>>(enc, src_mask, tgt_in, emb_table,
                                       W_ih0, W_hh0, b_ih0, b_hh0,
                                       W_ih1, W_hh1, b_ih1, b_hh1,
                                       Wq, vvec);

    // split dc -> bf16 hi/lo
    {
        size_t n4 = (size_t)Bn * Tn * KV / 4;
        split_kernel<<<(unsigned)((n4 + 255) / 256), 256>>>(dc_ptr, ahi_p, alo_p, n4);
    }

    // logits via HMMA split-bf16 GEMM
    {
        dim3 grid((Bn * Tn) / 128, VOCn / 128);
        hmma_gemm_vocab<<<grid, 256, smem_bytes>>>(b_out, out);
    }
}

// round 6
// speedup vs baseline: 3.7672x; 1.1084x over previous
#include <cuda_runtime.h>
#include <cuda_bf16.h>
#include <math.h>
#include <stdint.h>

#define Bn   32
#define Sn   64
#define Tn   64
#define EMBn 256
#define HIDn 512
#define VOCn 32000
#define KV   1024      // 2*HID

#define NBLK 128
#define NTHR 256

// vocab GEMM tiling
#define BKv   64
#define NKC   (KV / BKv)              // 16 k-chunks
#define BLKB  (128 * BKv * 2)         // 16384 bytes per tile block
#define STGB  (4 * BLKB)              // 65536 bytes per stage (Ah, Al, Wh, Wl)

// ---------------- scratch state (device globals; no allocation) ----------------
__device__ __align__(16) float g_kproj[Bn * Sn * HIDn];
__device__ __align__(16) float g_h0[2][Bn * HIDn];
__device__ __align__(16) float g_h1[2][Bn * HIDn];
__device__ __align__(16) float g_ctx[2][Bn * HIDn];
__device__ __align__(16) float g_q[Bn * HIDn];
__device__ __align__(16) float g_e[Bn * Sn];
__device__ __align__(16) float g_dc[Bn * Tn * 2 * HIDn];

// tiled+swizzled bf16 panels: [row_tile][k_chunk][16KB block]
__device__ __align__(1024) __nv_bfloat16 g_whi[(size_t)VOCn * KV];
__device__ __align__(1024) __nv_bfloat16 g_wlo[(size_t)VOCn * KV];
__device__ __align__(1024) __nv_bfloat16 g_ahi[Bn * Tn * KV];
__device__ __align__(1024) __nv_bfloat16 g_alo[Bn * Tn * KV];

__device__ unsigned g_cnt;
__device__ volatile unsigned g_gen;

// ================= helpers =================
__device__ __forceinline__ uint32_t smem_u32(const void* p) {
    uint32_t a;
    asm("{ .reg .u64 t; cvta.to.shared.u64 t, %1; cvt.u32.u64 %0, t; }" : "=r"(a) : "l"(p));
    return a;
}

#define MBAR_INIT(addr, cnt) \
    asm volatile("mbarrier.init.shared.b64 [%0], %1;" :: "r"(addr), "r"(cnt) : "memory")
#define MBAR_EXPECT_TX(addr, bytes) \
    asm volatile("mbarrier.arrive.expect_tx.shared.b64 _, [%0], %1;" :: "r"(addr), "r"(bytes) : "memory")
#define MBAR_WAIT(addr, parity) do {                                            \
    uint32_t _m = (addr), _p = (parity), _d;                                    \
    asm volatile("{\n\t.reg .pred p;\n\t"                                       \
        "mbarrier.try_wait.parity.acquire.cta.shared::cta.b64 p, [%1], %2;\n\t" \
        "selp.b32 %0, 1, 0, p;\n\t}" : "=r"(_d) : "r"(_m), "r"(_p) : "memory"); \
    if (!_d) {                                                                  \
        asm volatile("{\n\t.reg .pred P1;\n\tWL_%=:\n\t"                        \
            "mbarrier.try_wait.parity.acquire.cta.shared::cta.b64 P1, [%0], %1, 0x989680;\n\t" \
            "@P1 bra.uni WD_%=;\n\tbra.uni WL_%=;\n\tWD_%=:\n\t}"               \
            :: "r"(_m), "r"(_p) : "memory");                                    \
    } } while (0)

__device__ __forceinline__ void bulk_g2s(uint32_t dst, const void* src,
                                         uint32_t bytes, uint32_t bar) {
    asm volatile(
        "cp.async.bulk.shared::cluster.global.mbarrier::complete_tx::bytes "
        "[%0], [%1], %2, [%3];"
        :: "r"(dst), "l"(src), "r"(bytes), "r"(bar) : "memory");
}

__device__ __forceinline__ void ldm4(uint32_t& r0, uint32_t& r1, uint32_t& r2,
                                     uint32_t& r3, uint32_t a) {
    asm volatile("ldmatrix.sync.aligned.m8n8.x4.shared.b16 {%0,%1,%2,%3}, [%4];"
                 : "=r"(r0), "=r"(r1), "=r"(r2), "=r"(r3) : "r"(a));
}

__device__ __forceinline__ void mma_bf16(float* c, const uint32_t* a,
                                         uint32_t b0, uint32_t b1) {
    asm volatile(
        "mma.sync.aligned.m16n8k16.row.col.f32.bf16.bf16.f32 "
        "{%0,%1,%2,%3}, {%4,%5,%6,%7}, {%8,%9}, {%0,%1,%2,%3};"
        : "+f"(c[0]), "+f"(c[1]), "+f"(c[2]), "+f"(c[3])
        : "r"(a[0]), "r"(a[1]), "r"(a[2]), "r"(a[3]), "r"(b0), "r"(b1));
}

// swizzle within a 16KB tile block (128 rows x 128 bytes): chunk' = chunk ^ (row&7)
__device__ __forceinline__ uint32_t swz(uint32_t off) {
    return off ^ (((off >> 7) & 7u) << 4);
}

// ================= split fp32 -> bf16 hi/lo, tiled + swizzled =================
// One thread per 8-element (16B) output chunk.
__global__ __launch_bounds__(256) void split_tiled_kernel(
    const float* __restrict__ src, __nv_bfloat16* __restrict__ hi,
    __nv_bfloat16* __restrict__ lo, int nchunks)
{
    int id = blockIdx.x * 256 + threadIdx.x;
    if (id >= nchunks) return;
    int n  = id >> 7;                 // 128 chunks per 1024-elem row
    int k0 = (id & 127) * 8;
    const float* s = src + (size_t)n * KV + k0;
    float4 x0 = *(const float4*)s;
    float4 x1 = *(const float4*)(s + 4);

    uint32_t hw[4], lw[4];
    float xs[8] = {x0.x, x0.y, x0.z, x0.w, x1.x, x1.y, x1.z, x1.w};
#pragma unroll
    for (int i = 0; i < 4; i++) {
        __nv_bfloat16 h0 = __float2bfloat16(xs[2 * i]);
        __nv_bfloat16 h1 = __float2bfloat16(xs[2 * i + 1]);
        __nv_bfloat162 hp, lp;
        hp.x = h0; hp.y = h1;
        lp.x = __float2bfloat16(xs[2 * i]     - __bfloat162float(h0));
        lp.y = __float2bfloat16(xs[2 * i + 1] - __bfloat162float(h1));
        hw[i] = *(uint32_t*)&hp;
        lw[i] = *(uint32_t*)&lp;
    }

    int nt = n >> 7, r = n & 127, kc = k0 >> 6;
    uint32_t off = swz((uint32_t)(r * 128 + (k0 & 63) * 2));
    size_t blk = ((size_t)nt * NKC + kc) * BLKB;
    *(uint4*)((char*)hi + blk + off) = make_uint4(hw[0], hw[1], hw[2], hw[3]);
    *(uint4*)((char*)lo + blk + off) = make_uint4(lw[0], lw[1], lw[2], lw[3]);
}

// ================= HMMA split-bf16 vocab GEMM (TMA-bulk staged) =================
// C[2048,32000] = (Ahi+Alo) x (Whi+Wlo)^T + bias.
// CTA tile 128x128; 8 warps 2(m)x4(n), warp tile 64x32; BK=64, 16 stages,
// double-buffered cp.async.bulk with mbarrier completion.
__global__ __launch_bounds__(256, 1) void hmma_gemm_vocab(
    const float* __restrict__ bias, float* __restrict__ C)
{
    extern __shared__ __align__(128) char sm[];
    __shared__ __align__(8) uint64_t mbar[2];
    __shared__ float sBias[128];

    const int tid  = threadIdx.x;
    const int wid  = tid >> 5;
    const int lane = tid & 31;
    const int m_t = blockIdx.x, n_t = blockIdx.y;
    const int m0 = m_t * 128,   n0 = n_t * 128;
    const int warp_m = wid & 1;
    const int warp_n = wid >> 1;

    if (tid < 128) sBias[tid] = bias[n0 + tid];

    const uint32_t smb = smem_u32(sm);
    const uint32_t mb  = smem_u32(mbar);

    const char* gAh = (const char*)g_ahi + (size_t)m_t * NKC * BLKB;
    const char* gAl = (const char*)g_alo + (size_t)m_t * NKC * BLKB;
    const char* gWh = (const char*)g_whi + (size_t)n_t * NKC * BLKB;
    const char* gWl = (const char*)g_wlo + (size_t)n_t * NKC * BLKB;

    if (tid == 0) { MBAR_INIT(mb, 1); MBAR_INIT(mb + 8, 1); }
    __syncthreads();

    auto issue = [&](int s, int buf) {
        uint32_t d   = smb + buf * STGB;
        uint32_t bar = mb + buf * 8;
        MBAR_EXPECT_TX(bar, (uint32_t)STGB);
        bulk_g2s(d,             gAh + (size_t)s * BLKB, BLKB, bar);
        bulk_g2s(d + BLKB,      gAl + (size_t)s * BLKB, BLKB, bar);
        bulk_g2s(d + 2 * BLKB,  gWh + (size_t)s * BLKB, BLKB, bar);
        bulk_g2s(d + 3 * BLKB,  gWl + (size_t)s * BLKB, BLKB, bar);
    };
    if (tid == 0) issue(0, 0);

    float acc[4][4][4];
#pragma unroll
    for (int mt = 0; mt < 4; mt++)
#pragma unroll
        for (int nt = 0; nt < 4; nt++)
#pragma unroll
            for (int r = 0; r < 4; r++) acc[mt][nt][r] = 0.f;

    // per-lane fragment address components (bytes within a tile block)
    const int a_row = warp_m * 64 + (lane & 15);                      // + mt*16
    const int a_cb  = (lane >> 4) * 16;                               // + koff*2
    const int b_row = warp_n * 32 + ((lane >> 4) << 3) + (lane & 7);  // + p*16
    const int b_cb  = ((lane >> 3) & 1) * 16;                         // + koff*2

    for (int s = 0; s < NKC; s++) {
        const int buf = s & 1;
        MBAR_WAIT(mb + buf * 8, (uint32_t)((s >> 1) & 1));
        if (tid == 0 && s + 1 < NKC) issue(s + 1, buf ^ 1);

        const uint32_t sA_h = smb + buf * STGB;
        const uint32_t sA_l = sA_h + BLKB;
        const uint32_t sW_h = sA_h + 2 * BLKB;
        const uint32_t sW_l = sA_h + 3 * BLKB;

#pragma unroll
        for (int koff = 0; koff < BKv; koff += 16) {
            uint32_t ah[4][4], al[4][4], bh[2][4], bl[2][4];
#pragma unroll
            for (int mt = 0; mt < 4; mt++) {
                uint32_t off = swz((uint32_t)((a_row + mt * 16) * 128 +
                                              a_cb + koff * 2));
                ldm4(ah[mt][0], ah[mt][1], ah[mt][2], ah[mt][3], sA_h + off);
                ldm4(al[mt][0], al[mt][1], al[mt][2], al[mt][3], sA_l + off);
            }
#pragma unroll
            for (int p = 0; p < 2; p++) {
                uint32_t off = swz((uint32_t)((b_row + p * 16) * 128 +
                                              b_cb + koff * 2));
                ldm4(bh[p][0], bh[p][1], bh[p][2], bh[p][3], sW_h + off);
                ldm4(bl[p][0], bl[p][1], bl[p][2], bl[p][3], sW_l + off);
            }
#pragma unroll
            for (int mt = 0; mt < 4; mt++) {
#pragma unroll
                for (int nt = 0; nt < 4; nt++) {
                    int p = nt >> 1, h = (nt & 1) * 2;
                    mma_bf16(acc[mt][nt], ah[mt], bh[p][h], bh[p][h + 1]);
                    mma_bf16(acc[mt][nt], ah[mt], bl[p][h], bl[p][h + 1]);
                    mma_bf16(acc[mt][nt], al[mt], bh[p][h], bh[p][h + 1]);
                }
            }
        }
        __syncthreads();   // all consumers done with buf before next issue into it
    }

    // epilogue
    const int er = (lane >> 2);
    const int ec = (lane & 3) * 2;
#pragma unroll
    for (int mt = 0; mt < 4; mt++) {
#pragma unroll
        for (int nt = 0; nt < 4; nt++) {
            int row  = m0 + warp_m * 64 + mt * 16 + er;
            int colL = warp_n * 32 + nt * 8 + ec;
            int col  = n0 + colL;
            float2 o0, o1;
            o0.x = acc[mt][nt][0] + sBias[colL];
            o0.y = acc[mt][nt][1] + sBias[colL + 1];
            o1.x = acc[mt][nt][2] + sBias[colL];
            o1.y = acc[mt][nt][3] + sBias[colL + 1];
            *(float2*)(C + (size_t)row * VOCn + col)       = o0;
            *(float2*)(C + (size_t)(row + 8) * VOCn + col) = o1;
        }
    }
}

// ---------------- grid-wide software barrier ----------------
__device__ __forceinline__ void gsync() {
    __syncthreads();
    if (threadIdx.x == 0) {
        unsigned gen0 = g_gen;
        __threadfence();
        unsigned arrived = atomicAdd(&g_cnt, 1u);
        if (arrived == NBLK - 1) {
            atomicExch(&g_cnt, 0u);
            __threadfence();
            g_gen = gen0 + 1u;
        } else {
            while (g_gen == gen0) { __nanosleep(64); }
        }
        __threadfence();
    }
    __syncthreads();
}

// ---------------- dot helpers ----------------
__device__ __forceinline__ void triple16(const float* __restrict__ sx,
    const float* __restrict__ w0, const float* __restrict__ w1,
    const float* __restrict__ w2, float& a0, float& a1, float& a2)
{
#pragma unroll
    for (int i = 0; i < 16; i++) {
        float4 x = *(const float4*)(sx + i * 4);
        float4 u = *(const float4*)(w0 + i * 4);
        float4 v = *(const float4*)(w1 + i * 4);
        float4 s = *(const float4*)(w2 + i * 4);
        a0 = fmaf(x.x, u.x, fmaf(x.y, u.y, fmaf(x.z, u.z, fmaf(x.w, u.w, a0))));
        a1 = fmaf(x.x, v.x, fmaf(x.y, v.y, fmaf(x.z, v.z, fmaf(x.w, v.w, a1))));
        a2 = fmaf(x.x, s.x, fmaf(x.y, s.y, fmaf(x.z, s.z, fmaf(x.w, s.w, a2))));
    }
}
__device__ __forceinline__ void single16(const float* __restrict__ sx,
    const float* __restrict__ w0, float& a0)
{
#pragma unroll
    for (int i = 0; i < 16; i++) {
        float4 x = *(const float4*)(sx + i * 4);
        float4 u = *(const float4*)(w0 + i * 4);
        a0 = fmaf(x.x, u.x, fmaf(x.y, u.y, fmaf(x.z, u.z, fmaf(x.w, u.w, a0))));
    }
}

// ---------------- persistent recurrence kernel ----------------
__global__ __launch_bounds__(NTHR, 1) void decoder_persistent(
    const float* __restrict__ enc, const unsigned char* __restrict__ mask,
    const int* __restrict__ tgt, const float* __restrict__ emb,
    const float* __restrict__ Wih0, const float* __restrict__ Whh0,
    const float* __restrict__ bih0, const float* __restrict__ bhh0,
    const float* __restrict__ Wih1, const float* __restrict__ Whh1,
    const float* __restrict__ bih1, const float* __restrict__ bhh1,
    const float* __restrict__ Wq, const float* __restrict__ vvec)
{
    __shared__ __align__(16) float sX[2][Bn][132];
    __shared__ float sred[2][4][4][32];
    __shared__ int   sTok[Bn];
    __shared__ float sA[Sn];

    const int tid   = threadIdx.x;
    const int bid   = blockIdx.x;
    const int w     = tid >> 5;
    const int lane  = tid & 31;
    const int jl    = w & 3;
    const int khalf = w >> 2;
    const int j     = bid * 4 + jl;

    {
        int base = bid * 128;
        if (tid < 128) {
            g_h0[0][base + tid]  = 0.f;
            g_h1[0][base + tid]  = 0.f;
            g_ctx[0][base + tid] = 0.f;
        }
    }
    gsync();

    for (int t = 0; t < Tn; t++) {
        const int p = t & 1;
        const float* h0p  = g_h0[p];     float* h0n  = g_h0[1 - p];
        const float* h1p  = g_h1[p];     float* h1n  = g_h1[1 - p];
        const float* ctxp = g_ctx[p];    float* ctxn = g_ctx[1 - p];

        // Phase 1: GRU0
        if (tid < Bn) sTok[tid] = tgt[tid * Tn + t];
        __syncthreads();
        {
            float4 rv[4];
            auto stage = [&](int c) {
#pragma unroll
                for (int r = 0; r < 4; r++) {
                    int idx = r * 256 + tid;
                    int b = idx >> 5, q = idx & 31;
                    const float* src;
                    if (c < 2)      src = emb + (size_t)sTok[b] * EMBn + c * 128;
                    else if (c < 6) src = ctxp + b * HIDn + (c - 2) * 128;
                    else            src = h0p + b * HIDn + (c - 6) * 128;
                    rv[r] = *(const float4*)(src + q * 4);
                }
            };
            auto sts = [&](int buf) {
#pragma unroll
                for (int r = 0; r < 4; r++) {
                    int idx = r * 256 + tid;
                    int b = idx >> 5, q = idx & 31;
                    *(float4*)&sX[buf][b][q * 4] = rv[r];
                }
            };
            float ar = 0.f, az = 0.f, anx = 0.f, anh = 0.f;
            stage(0); sts(0); __syncthreads();
            for (int c = 0; c < 10; c++) {
                if (c < 9) stage(c + 1);
                const float* sx = &sX[c & 1][lane][khalf * 64];
                if (c < 6) {
                    int col = c * 128 + khalf * 64;
                    triple16(sx, Wih0 + (size_t)j * 768 + col,
                             Wih0 + (size_t)(j + 512) * 768 + col,
                             Wih0 + (size_t)(j + 1024) * 768 + col, ar, az, anx);
                } else {
                    int col = (c - 6) * 128 + khalf * 64;
                    triple16(sx, Whh0 + (size_t)j * 512 + col,
                             Whh0 + (size_t)(j + 512) * 512 + col,
                             Whh0 + (size_t)(j + 1024) * 512 + col, ar, az, anh);
                }
                if (c < 9) sts((c + 1) & 1);
                __syncthreads();
            }
            sred[khalf][jl][0][lane] = ar;
            sred[khalf][jl][1][lane] = az;
            sred[khalf][jl][2][lane] = anx;
            sred[khalf][jl][3][lane] = anh;
            __syncthreads();
            if (khalf == 0) {
                ar  += sred[1][jl][0][lane];
                az  += sred[1][jl][1][lane];
                anx += sred[1][jl][2][lane];
                anh += sred[1][jl][3][lane];
                float r = 1.f / (1.f + expf(-(ar + bih0[j] + bhh0[j])));
                float z = 1.f / (1.f + expf(-(az + bih0[j + 512] + bhh0[j + 512])));
                float n = tanhf(anx + bih0[j + 1024] + r * (anh + bhh0[j + 1024]));
                float hp = h0p[lane * HIDn + j];
                h0n[lane * HIDn + j] = (1.f - z) * n + z * hp;
            }
        }
        gsync();

        // Phase 2: GRU1
        {
            float4 rv[4];
            auto stage = [&](int c) {
#pragma unroll
                for (int r = 0; r < 4; r++) {
                    int idx = r * 256 + tid;
                    int b = idx >> 5, q = idx & 31;
                    const float* src = (c < 4) ? (h0n + b * HIDn + c * 128)
                                               : (h1p + b * HIDn + (c - 4) * 128);
                    rv[r] = *(const float4*)(src + q * 4);
                }
            };
            auto sts = [&](int buf) {
#pragma unroll
                for (int r = 0; r < 4; r++) {
                    int idx = r * 256 + tid;
                    int b = idx >> 5, q = idx & 31;
                    *(float4*)&sX[buf][b][q * 4] = rv[r];
                }
            };
            float ar = 0.f, az = 0.f, anx = 0.f, anh = 0.f;
            stage(0); sts(0); __syncthreads();
            for (int c = 0; c < 8; c++) {
                if (c < 7) stage(c + 1);
                const float* sx = &sX[c & 1][lane][khalf * 64];
                if (c < 4) {
                    int col = c * 128 + khalf * 64;
                    triple16(sx, Wih1 + (size_t)j * 512 + col,
                             Wih1 + (size_t)(j + 512) * 512 + col,
                             Wih1 + (size_t)(j + 1024) * 512 + col, ar, az, anx);
                } else {
                    int col = (c - 4) * 128 + khalf * 64;
                    triple16(sx, Whh1 + (size_t)j * 512 + col,
                             Whh1 + (size_t)(j + 512) * 512 + col,
                             Whh1 + (size_t)(j + 1024) * 512 + col, ar, az, anh);
                }
                if (c < 7) sts((c + 1) & 1);
                __syncthreads();
            }
            sred[khalf][jl][0][lane] = ar;
            sred[khalf][jl][1][lane] = az;
            sred[khalf][jl][2][lane] = anx;
            sred[khalf][jl][3][lane] = anh;
            __syncthreads();
            if (khalf == 0) {
                ar  += sred[1][jl][0][lane];
                az  += sred[1][jl][1][lane];
                anx += sred[1][jl][2][lane];
                anh += sred[1][jl][3][lane];
                float r = 1.f / (1.f + expf(-(ar + bih1[j] + bhh1[j])));
                float z = 1.f / (1.f + expf(-(az + bih1[j + 512] + bhh1[j + 512])));
                float n = tanhf(anx + bih1[j + 1024] + r * (anh + bhh1[j + 1024]));
                float hp = h1p[lane * HIDn + j];
                float hnew = (1.f - z) * n + z * hp;
                h1n[lane * HIDn + j] = hnew;
                g_dc[((size_t)lane * Tn + t) * (2 * HIDn) + j] = hnew;
            }
        }
        gsync();

        // Phase 3: q = dec @ Wq^T
        {
            float4 rv[4];
            auto stage = [&](int c) {
#pragma unroll
                for (int r = 0; r < 4; r++) {
                    int idx = r * 256 + tid;
                    int b = idx >> 5, q = idx & 31;
                    rv[r] = *(const float4*)(h1n + b * HIDn + c * 128 + q * 4);
                }
            };
            auto sts = [&](int buf) {
#pragma unroll
                for (int r = 0; r < 4; r++) {
                    int idx = r * 256 + tid;
                    int b = idx >> 5, q = idx & 31;
                    *(float4*)&sX[buf][b][q * 4] = rv[r];
                }
            };
            float aq = 0.f;
            stage(0); sts(0); __syncthreads();
            for (int c = 0; c < 4; c++) {
                if (c < 3) stage(c + 1);
                const float* sx = &sX[c & 1][lane][khalf * 64];
                single16(sx, Wq + (size_t)j * 512 + c * 128 + khalf * 64, aq);
                if (c < 3) sts((c + 1) & 1);
                __syncthreads();
            }
            sred[khalf][jl][0][lane] = aq;
            __syncthreads();
            if (khalf == 0) {
                aq += sred[1][jl][0][lane];
                g_q[lane * HIDn + j] = aq;
            }
        }
        gsync();

        // Phase 4: scores
        {
#pragma unroll
            for (int r = 0; r < 2; r++) {
                int pi = bid * 16 + w * 2 + r;
                int b = pi >> 6, s = pi & 63;
                const float* qb = g_q + b * HIDn;
                const float* kp = g_kproj + ((size_t)b * Sn + s) * HIDn;
                float acc = 0.f;
#pragma unroll
                for (int i = 0; i < 16; i++) {
                    int h = lane + i * 32;
                    acc = fmaf(vvec[h], tanhf(qb[h] + kp[h]), acc);
                }
#pragma unroll
                for (int o = 16; o; o >>= 1) acc += __shfl_xor_sync(0xFFFFFFFFu, acc, o);
                if (lane == 0) g_e[b * Sn + s] = mask[b * Sn + s] ? -1e9f : acc;
            }
        }
        gsync();

        // Phase 5: softmax + ctx
        {
            const int b  = bid >> 2;
            const int hs = (bid & 3) * 128;
            if (w == 0) {
                float e0 = g_e[b * Sn + lane];
                float e1 = g_e[b * Sn + 32 + lane];
                float m = fmaxf(e0, e1);
#pragma unroll
                for (int o = 16; o; o >>= 1) m = fmaxf(m, __shfl_xor_sync(0xFFFFFFFFu, m, o));
                float x0 = expf(e0 - m), x1 = expf(e1 - m);
                float ssum = x0 + x1;
#pragma unroll
                for (int o = 16; o; o >>= 1) ssum += __shfl_xor_sync(0xFFFFFFFFu, ssum, o);
                float rinv = 1.f / ssum;
                sA[lane]      = x0 * rinv;
                sA[lane + 32] = x1 * rinv;
            }
            __syncthreads();
            if (tid < 128) {
                int h = hs + tid;
                const float* eb = enc + (size_t)b * Sn * HIDn + h;
                float c = 0.f;
#pragma unroll
                for (int s = 0; s < Sn; s++) c = fmaf(sA[s], eb[(size_t)s * HIDn], c);
                ctxn[b * HIDn + h] = c;
                g_dc[((size_t)b * Tn + t) * (2 * HIDn) + HIDn + h] = c;
            }
        }
        gsync();
    }
}

// ---------------- small fp32 GEMM for kproj ----------------
#define GBM 64
#define GBN 64
#define GBK 16
__global__ __launch_bounds__(256) void gemm_abt_kernel(
    const float* __restrict__ A, const float* __restrict__ B,
    float* __restrict__ C, int M, int N, int K)
{
    __shared__ __align__(16) float As[GBK][GBM + 4];
    __shared__ __align__(16) float Bs[GBK][GBN + 4];
    const int tid = threadIdx.x;
    const int rowBase = blockIdx.y * GBM;
    const int colBase = blockIdx.x * GBN;
    const int tm = tid >> 4;
    const int tn = tid & 15;
    const int lr  = tid >> 2;
    const int lk4 = (tid & 3) * 4;

    float acc[4][4];
#pragma unroll
    for (int i = 0; i < 4; i++)
#pragma unroll
        for (int jj = 0; jj < 4; jj++) acc[i][jj] = 0.f;

    const float* Aptr = A + (size_t)(rowBase + lr) * K + lk4;
    const float* Bptr = B + (size_t)(colBase + lr) * K + lk4;
    for (int kt = 0; kt < K; kt += GBK) {
        float4 a4 = *(const float4*)(Aptr + kt);
        float4 b4 = *(const float4*)(Bptr + kt);
        As[lk4 + 0][lr] = a4.x; As[lk4 + 1][lr] = a4.y;
        As[lk4 + 2][lr] = a4.z; As[lk4 + 3][lr] = a4.w;
        Bs[lk4 + 0][lr] = b4.x; Bs[lk4 + 1][lr] = b4.y;
        Bs[lk4 + 2][lr] = b4.z; Bs[lk4 + 3][lr] = b4.w;
        __syncthreads();
#pragma unroll
        for (int kk = 0; kk < GBK; kk++) {
            float4 av = *(const float4*)(&As[kk][tm * 4]);
            float4 bv = *(const float4*)(&Bs[kk][tn * 4]);
            float ar[4] = {av.x, av.y, av.z, av.w};
            float br[4] = {bv.x, bv.y, bv.z, bv.w};
#pragma unroll
            for (int i = 0; i < 4; i++)
#pragma unroll
                for (int jj = 0; jj < 4; jj++)
                    acc[i][jj] = fmaf(ar[i], br[jj], acc[i][jj]);
        }
        __syncthreads();
    }
#pragma unroll
    for (int i = 0; i < 4; i++) {
        float4 o;
        o.x = acc[i][0]; o.y = acc[i][1]; o.z = acc[i][2]; o.w = acc[i][3];
        *(float4*)(C + (size_t)(rowBase + tm * 4 + i) * N + colBase + tn * 4) = o;
    }
}

// ---------------- launch ----------------
extern "C" void kernel_launch(void* const* d_in, const int* in_sizes, int n_in,
                              void* d_out, int out_size)
{
    const float*         enc       = (const float*)d_in[0];
    const unsigned char* src_mask  = (const unsigned char*)d_in[1];
    const int*           tgt_in    = (const int*)d_in[2];
    const float*         emb_table = (const float*)d_in[3];
    const float*         W_ih0     = (const float*)d_in[4];
    const float*         W_hh0     = (const float*)d_in[5];
    const float*         b_ih0     = (const float*)d_in[6];
    const float*         b_hh0     = (const float*)d_in[7];
    const float*         W_ih1     = (const float*)d_in[8];
    const float*         W_hh1     = (const float*)d_in[9];
    const float*         b_ih1     = (const float*)d_in[10];
    const float*         b_hh1     = (const float*)d_in[11];
    const float*         Wq        = (const float*)d_in[12];
    const float*         Wk        = (const float*)d_in[13];
    const float*         vvec      = (const float*)d_in[14];
    const float*         W_out     = (const float*)d_in[15];
    const float*         b_out     = (const float*)d_in[16];
    float*               out       = (float*)d_out;

    float* kproj_ptr = nullptr;
    float* dc_ptr    = nullptr;
    __nv_bfloat16 *whi_p = nullptr, *wlo_p = nullptr, *ahi_p = nullptr, *alo_p = nullptr;
    cudaGetSymbolAddress((void**)&kproj_ptr, g_kproj);
    cudaGetSymbolAddress((void**)&dc_ptr, g_dc);
    cudaGetSymbolAddress((void**)&whi_p, g_whi);
    cudaGetSymbolAddress((void**)&wlo_p, g_wlo);
    cudaGetSymbolAddress((void**)&ahi_p, g_ahi);
    cudaGetSymbolAddress((void**)&alo_p, g_alo);

    const int smem_bytes = 2 * STGB;   // 131072
    cudaFuncSetAttribute(hmma_gemm_vocab,
                         cudaFuncAttributeMaxDynamicSharedMemorySize, smem_bytes);

    // split W_out -> tiled/swizzled bf16 hi/lo
    {
        int nchunks = VOCn * (KV / 8);
        split_tiled_kernel<<<(nchunks + 255) / 256, 256>>>(W_out, whi_p, wlo_p, nchunks);
    }

    // k_proj = enc_out @ Wk^T
    {
        dim3 grid(HIDn / GBN, (Bn * Sn) / GBM);
        gemm_abt_kernel<<<grid, 256>>>(enc, Wk, kproj_ptr, Bn * Sn, HIDn, HIDn);
    }

    // full recurrence
    decoder_persistent<<<NBLK, NTHR>>>(enc, src_mask, tgt_in, emb_table,
                                       W_ih0, W_hh0, b_ih0, b_hh0,
                                       W_ih1, W_hh1, b_ih1, b_hh1,
                                       Wq, vvec);

    // split dc -> tiled/swizzled bf16 hi/lo
    {
        int nchunks = Bn * Tn * (KV / 8);
        split_tiled_kernel<<<(nchunks + 255) / 256, 256>>>(dc_ptr, ahi_p, alo_p, nchunks);
    }

    // logits via HMMA split-bf16 GEMM (TMA-bulk staged)
    {
        dim3 grid((Bn * Tn) / 128, VOCn / 128);
        hmma_gemm_vocab<<<grid, 256, smem_bytes>>>(b_out, out);
    }
}